// round 2
// baseline (speedup 1.0000x reference)
#include <cuda_runtime.h>
#include <math.h>

#define B_   4
#define C_   2048
#define H_   48
#define N_   2304   /* 48*48 */
#define CAM_ 384

#define BM   128
#define BN   128
#define BK   16
#define LDS_ 132    /* BM + 4 pad */

// ---------------- scratch (device globals: allocation-free) ----------------
__device__ float g_q  [B_ * C_ * N_];
__device__ float g_k  [B_ * C_ * N_];
__device__ float g_att[B_ * N_ * N_];
__device__ float g_qn2[B_ * N_];
__device__ float g_kn2[B_ * N_];
__device__ float g_mask[B_ * N_];
__device__ double g_sum;
__device__ unsigned long long g_cnt;

// ---------------- init ------------------------------------------------------
__global__ void init_kernel() {
    int i = blockIdx.x * blockDim.x + threadIdx.x;
    if (i < B_ * N_) { g_qn2[i] = 0.f; g_kn2[i] = 0.f; }
    if (i == 0) { g_sum = 0.0; g_cnt = 0ull; }
}

// ---------------- mask: bilinear resize (align_corners) + >0 ----------------
__global__ void mask_kernel(const float* __restrict__ cam) {
    int i = blockIdx.x * blockDim.x + threadIdx.x;
    if (i >= B_ * N_) return;
    int b = i / N_, p = i % N_;
    int oy = p / H_, ox = p % H_;
    const float step = 383.0f / 47.0f;
    float sy = (float)oy * step;
    float sx = (float)ox * step;
    int y0 = (int)floorf(sy); y0 = max(0, min(y0, CAM_ - 1));
    int x0 = (int)floorf(sx); x0 = max(0, min(x0, CAM_ - 1));
    int y1 = min(y0 + 1, CAM_ - 1);
    int x1 = min(x0 + 1, CAM_ - 1);
    float wy = sy - (float)y0;
    float wx = sx - (float)x0;
    const float* cb = cam + (size_t)b * CAM_ * CAM_;
    float v00 = cb[y0 * CAM_ + x0]; v00 = (v00 == 255.0f) ? 0.f : v00;
    float v01 = cb[y0 * CAM_ + x1]; v01 = (v01 == 255.0f) ? 0.f : v01;
    float v10 = cb[y1 * CAM_ + x0]; v10 = (v10 == 255.0f) ? 0.f : v10;
    float v11 = cb[y1 * CAM_ + x1]; v11 = (v11 == 255.0f) ? 0.f : v11;
    float top = (1.f - wx) * v00 + wx * v01;
    float bot = (1.f - wx) * v10 + wx * v11;
    float val = (1.f - wy) * top + wy * bot;
    g_mask[i] = (val > 0.f) ? 1.f : 0.f;
}

// ---------------- 128x128x16 fp32 GEMM, 256 thr, 8x8 microtile, dbl-buf ----
// AMODE 0: A is [M,K] row-major (transpose on SMEM store); AMODE 1: A is [K,M]
// BMODE 1: B is [K,N] (direct); BMODE 0: B is [N,K] (transpose)
// EPI 0: +bias[m], store C, accumulate per-column sum-of-squares (atomic)
// EPI 1: store C
// EPI 2: no store; loss: r=(x - gamma*acc)^2 -> g_sum/g_cnt
template <int AMODE, int BMODE, int EPI>
__global__ void __launch_bounds__(256, 2)
gemm_kernel(const float* __restrict__ Ag, const float* __restrict__ Bg,
            float* __restrict__ Cg, const float* __restrict__ bias,
            const float* __restrict__ Xg, float* __restrict__ colnorm2,
            const float* __restrict__ gptr,
            int Ncols, int K, int lda, int ldb, int ldc,
            long long sA, long long sB, long long sC)
{
    __shared__ float As[2][BK][LDS_];
    __shared__ float Bs[2][BK][LDS_];

    const int b  = blockIdx.z;
    const float* A  = Ag + (size_t)b * sA;
    const float* Bp = Bg + (size_t)b * sB;
    const int n0 = blockIdx.x * BN;
    const int m0 = blockIdx.y * BM;
    const int tid = threadIdx.x;
    const int tx = tid & 15, ty = tid >> 4;

    // loader indices
    const int t_r = tid >> 2;          // 0..63 (transpose modes)
    const int t_c = (tid & 3) << 2;    // 0,4,8,12
    const int d_k = tid >> 5;          // 0..7  (direct modes)
    const int d_m = (tid & 31) << 2;   // 0..124

    float4 ra[2], rb[2];
    float acc[8][8] = {};

    auto loadA = [&](int kt) {
        if (AMODE == 0) {
            ra[0] = *(const float4*)(A + (size_t)(m0 + t_r)      * lda + kt + t_c);
            ra[1] = *(const float4*)(A + (size_t)(m0 + 64 + t_r) * lda + kt + t_c);
        } else {
            ra[0] = *(const float4*)(A + (size_t)(kt + d_k)     * lda + m0 + d_m);
            ra[1] = *(const float4*)(A + (size_t)(kt + 8 + d_k) * lda + m0 + d_m);
        }
    };
    auto loadB = [&](int kt) {
        if (BMODE == 1) {
            rb[0] = *(const float4*)(Bp + (size_t)(kt + d_k)     * ldb + n0 + d_m);
            rb[1] = *(const float4*)(Bp + (size_t)(kt + 8 + d_k) * ldb + n0 + d_m);
        } else {
            rb[0] = *(const float4*)(Bp + (size_t)(n0 + t_r)      * ldb + kt + t_c);
            rb[1] = *(const float4*)(Bp + (size_t)(n0 + 64 + t_r) * ldb + kt + t_c);
        }
    };
    auto storeAB = [&](int buf) {
        if (AMODE == 0) {
            As[buf][t_c + 0][t_r] = ra[0].x; As[buf][t_c + 1][t_r] = ra[0].y;
            As[buf][t_c + 2][t_r] = ra[0].z; As[buf][t_c + 3][t_r] = ra[0].w;
            As[buf][t_c + 0][t_r + 64] = ra[1].x; As[buf][t_c + 1][t_r + 64] = ra[1].y;
            As[buf][t_c + 2][t_r + 64] = ra[1].z; As[buf][t_c + 3][t_r + 64] = ra[1].w;
        } else {
            *(float4*)&As[buf][d_k][d_m]     = ra[0];
            *(float4*)&As[buf][d_k + 8][d_m] = ra[1];
        }
        if (BMODE == 1) {
            *(float4*)&Bs[buf][d_k][d_m]     = rb[0];
            *(float4*)&Bs[buf][d_k + 8][d_m] = rb[1];
        } else {
            Bs[buf][t_c + 0][t_r] = rb[0].x; Bs[buf][t_c + 1][t_r] = rb[0].y;
            Bs[buf][t_c + 2][t_r] = rb[0].z; Bs[buf][t_c + 3][t_r] = rb[0].w;
            Bs[buf][t_c + 0][t_r + 64] = rb[1].x; Bs[buf][t_c + 1][t_r + 64] = rb[1].y;
            Bs[buf][t_c + 2][t_r + 64] = rb[1].z; Bs[buf][t_c + 3][t_r + 64] = rb[1].w;
        }
    };

    const int KT = K / BK;
    loadA(0); loadB(0);
    storeAB(0);
    __syncthreads();

    int buf = 0;
    for (int t = 0; t < KT; ++t) {
        if (t + 1 < KT) { loadA((t + 1) * BK); loadB((t + 1) * BK); }
        #pragma unroll
        for (int kk = 0; kk < BK; kk++) {
            float4 a0 = *(const float4*)&As[buf][kk][ty * 4];
            float4 a1 = *(const float4*)&As[buf][kk][ty * 4 + 64];
            float4 b0 = *(const float4*)&Bs[buf][kk][tx * 4];
            float4 b1 = *(const float4*)&Bs[buf][kk][tx * 4 + 64];
            float av[8] = {a0.x, a0.y, a0.z, a0.w, a1.x, a1.y, a1.z, a1.w};
            float bv[8] = {b0.x, b0.y, b0.z, b0.w, b1.x, b1.y, b1.z, b1.w};
            #pragma unroll
            for (int i = 0; i < 8; i++)
                #pragma unroll
                for (int j = 0; j < 8; j++)
                    acc[i][j] += av[i] * bv[j];
        }
        if (t + 1 < KT) {
            storeAB(buf ^ 1);
            __syncthreads();
            buf ^= 1;
        }
    }

    if (EPI == 0) {
        float* Cb = Cg + (size_t)b * sC;
        float cpart[8] = {};
        #pragma unroll
        for (int i = 0; i < 8; i++) {
            int rm = m0 + ty * 4 + (i & 3) + (i >> 2) * 64;
            float bv = bias[rm];
            float4 v0, v1;
            v0.x = acc[i][0] + bv; v0.y = acc[i][1] + bv;
            v0.z = acc[i][2] + bv; v0.w = acc[i][3] + bv;
            v1.x = acc[i][4] + bv; v1.y = acc[i][5] + bv;
            v1.z = acc[i][6] + bv; v1.w = acc[i][7] + bv;
            *(float4*)(Cb + (size_t)rm * ldc + n0 + tx * 4)      = v0;
            *(float4*)(Cb + (size_t)rm * ldc + n0 + tx * 4 + 64) = v1;
            cpart[0] += v0.x * v0.x; cpart[1] += v0.y * v0.y;
            cpart[2] += v0.z * v0.z; cpart[3] += v0.w * v0.w;
            cpart[4] += v1.x * v1.x; cpart[5] += v1.y * v1.y;
            cpart[6] += v1.z * v1.z; cpart[7] += v1.w * v1.w;
        }
        __syncthreads();                 // all compute reads of SMEM done
        float* red = &As[0][0][0];       // [16][128] view
        #pragma unroll
        for (int j = 0; j < 8; j++)
            red[ty * 128 + tx * 4 + (j & 3) + (j >> 2) * 64] = cpart[j];
        __syncthreads();
        if (tid < 128) {
            float s = 0.f;
            #pragma unroll
            for (int r = 0; r < 16; r++) s += red[r * 128 + tid];
            atomicAdd(&colnorm2[(size_t)b * Ncols + n0 + tid], s);
        }
    } else if (EPI == 1) {
        float* Cb = Cg + (size_t)b * sC;
        #pragma unroll
        for (int i = 0; i < 8; i++) {
            int rm = m0 + ty * 4 + (i & 3) + (i >> 2) * 64;
            float4 v0 = {acc[i][0], acc[i][1], acc[i][2], acc[i][3]};
            float4 v1 = {acc[i][4], acc[i][5], acc[i][6], acc[i][7]};
            *(float4*)(Cb + (size_t)rm * ldc + n0 + tx * 4)      = v0;
            *(float4*)(Cb + (size_t)rm * ldc + n0 + tx * 4 + 64) = v1;
        }
    } else {
        const float gm = gptr[0];
        const float* Xb = Xg + (size_t)b * sA;   // x shares A's batch stride
        float lsum = 0.f;
        unsigned lcnt = 0;
        #pragma unroll
        for (int i = 0; i < 8; i++) {
            int rm = m0 + ty * 4 + (i & 3) + (i >> 2) * 64;
            float4 x0 = *(const float4*)(Xb + (size_t)rm * ldc + n0 + tx * 4);
            float4 x1 = *(const float4*)(Xb + (size_t)rm * ldc + n0 + tx * 4 + 64);
            float xv[8] = {x0.x, x0.y, x0.z, x0.w, x1.x, x1.y, x1.z, x1.w};
            #pragma unroll
            for (int j = 0; j < 8; j++) {
                float d = xv[j] - gm * acc[i][j];
                float rr = d * d;
                lsum += rr;
                lcnt += (rr != 0.f) ? 1u : 0u;
            }
        }
        __syncthreads();
        float*    rs = &As[0][0][0];
        unsigned* rc = (unsigned*)&Bs[0][0][0];
        rs[tid] = lsum; rc[tid] = lcnt;
        __syncthreads();
        for (int s = 128; s > 0; s >>= 1) {
            if (tid < s) { rs[tid] += rs[tid + s]; rc[tid] += rc[tid + s]; }
            __syncthreads();
        }
        if (tid == 0) {
            atomicAdd(&g_sum, (double)rs[0]);
            atomicAdd(&g_cnt, (unsigned long long)rc[0]);
        }
    }
}

// ---------------- row softmax (in-place on g_att) ---------------------------
__global__ void __launch_bounds__(256)
softmax_kernel(float* __restrict__ att)
{
    __shared__ float row[N_];
    __shared__ float red[256];
    const int n = blockIdx.x, b = blockIdx.y;
    const int tid = threadIdx.x;
    float* Ar = att + ((size_t)b * N_ + n) * N_;
    const float qs = g_qn2[b * N_ + n];

    float lmax = -INFINITY;
    for (int m = tid; m < N_; m += 256) {
        float v = Ar[m] * rsqrtf(qs * g_kn2[b * N_ + m]);
        row[m] = v;
        lmax = fmaxf(lmax, v);
    }
    red[tid] = lmax; __syncthreads();
    for (int s = 128; s > 0; s >>= 1) {
        if (tid < s) red[tid] = fmaxf(red[tid], red[tid + s]);
        __syncthreads();
    }
    float mx = red[0];
    __syncthreads();
    float lsum = 0.f;
    for (int m = tid; m < N_; m += 256) {
        float e = __expf(row[m] - mx);
        row[m] = e;
        lsum += e;
    }
    red[tid] = lsum; __syncthreads();
    for (int s = 128; s > 0; s >>= 1) {
        if (tid < s) red[tid] += red[tid + s];
        __syncthreads();
    }
    float scale = g_mask[b * N_ + n] / red[0];
    for (int m = tid; m < N_; m += 256) Ar[m] = row[m] * scale;
}

// ---------------- finalize --------------------------------------------------
__global__ void finalize_kernel(float* out) {
    out[0] = (float)(g_sum / (double)g_cnt);
}

// ---------------- launch ----------------------------------------------------
extern "C" void kernel_launch(void* const* d_in, const int* in_sizes, int n_in,
                              void* d_out, int out_size)
{
    const float* x     = (const float*)d_in[0];
    const float* cam   = (const float*)d_in[1];
    const float* Wq    = (const float*)d_in[2];
    const float* bq    = (const float*)d_in[3];
    const float* Wk    = (const float*)d_in[4];
    const float* bk    = (const float*)d_in[5];
    const float* gamma = (const float*)d_in[6];

    float *pq, *pk, *patt, *pqn2, *pkn2;
    cudaGetSymbolAddress((void**)&pq,   g_q);
    cudaGetSymbolAddress((void**)&pk,   g_k);
    cudaGetSymbolAddress((void**)&patt, g_att);
    cudaGetSymbolAddress((void**)&pqn2, g_qn2);
    cudaGetSymbolAddress((void**)&pkn2, g_kn2);

    const long long sCN = (long long)C_ * N_;
    const long long sNN = (long long)N_ * N_;

    init_kernel<<<(B_ * N_ + 255) / 256, 256>>>();
    mask_kernel<<<(B_ * N_ + 255) / 256, 256>>>(cam);

    // q = Wq * x + bq  (fused column-norm^2)
    gemm_kernel<0, 1, 0><<<dim3(N_ / BN, C_ / BM, B_), 256>>>(
        Wq, x, pq, bq, nullptr, pqn2, nullptr,
        N_, C_, C_, N_, N_, 0LL, sCN, sCN);
    // k = Wk * x + bk
    gemm_kernel<0, 1, 0><<<dim3(N_ / BN, C_ / BM, B_), 256>>>(
        Wk, x, pk, bk, nullptr, pkn2, nullptr,
        N_, C_, C_, N_, N_, 0LL, sCN, sCN);
    // energy = q^T k
    gemm_kernel<1, 1, 1><<<dim3(N_ / BN, N_ / BM, B_), 256>>>(
        pq, pk, patt, nullptr, nullptr, nullptr, nullptr,
        N_, C_, N_, N_, N_, sCN, sCN, sNN);
    // softmax(energy / (|q||k|)) * mask, in place
    softmax_kernel<<<dim3(N_, B_), 256>>>(patt);
    // new_x = x * atten^T, fused loss
    gemm_kernel<0, 0, 2><<<dim3(N_ / BN, C_ / BM, B_), 256>>>(
        x, patt, nullptr, nullptr, x, nullptr, gamma,
        N_, N_, N_, N_, N_, sCN, sNN, 0LL);

    finalize_kernel<<<1, 1>>>((float*)d_out);
}

// round 4
// speedup vs baseline: 12.3382x; 12.3382x over previous
#include <cuda_runtime.h>
#include <cuda_bf16.h>
#include <math.h>
#include <stdint.h>

#define B_   4
#define C_   2048
#define H_   48
#define N_   2304
#define CAM_ 384

#define TM   128
#define TN   128
#define TK   64
#define STAGE 32768              /* A: 128*128B + B: 128*128B */
#define SMEM_DYN (2*STAGE + 1024)

// ---------------- scratch (device globals) ----------------------------------
__device__ __nv_bfloat16 g_xb [B_ * C_ * N_];   // x bf16  [C,N]
__device__ __nv_bfloat16 g_xt [B_ * N_ * C_];   // x^T bf16 [N,C]
__device__ __nv_bfloat16 g_wqb[C_ * C_];
__device__ __nv_bfloat16 g_wkb[C_ * C_];
__device__ __nv_bfloat16 g_qr [B_ * N_ * C_];
__device__ __nv_bfloat16 g_kr [B_ * N_ * C_];
__device__ float         g_att [B_ * N_ * N_];
__device__ __nv_bfloat16 g_attb[B_ * N_ * N_];
__device__ float g_qn2[B_ * N_];
__device__ float g_kn2[B_ * N_];
__device__ float g_mask[B_ * N_];
__device__ double g_sum;
__device__ unsigned long long g_cnt;

// ---------------- helpers -----------------------------------------------------
__device__ __forceinline__ uint32_t smem_u32(const void* p) {
    uint32_t a;
    asm("{ .reg .u64 t; cvta.to.shared.u64 t, %1; cvt.u32.u64 %0, t; }"
        : "=r"(a) : "l"(p));
    return a;
}
__device__ __forceinline__ void cp_async16(uint32_t dst, const void* src) {
    asm volatile("cp.async.cg.shared.global [%0], [%1], 16;"
                 :: "r"(dst), "l"(src) : "memory");
}
__device__ __forceinline__ void cp_commit() {
    asm volatile("cp.async.commit_group;" ::: "memory");
}
__device__ __forceinline__ void cp_wait0() {
    asm volatile("cp.async.wait_group 0;" ::: "memory");
}
__device__ __forceinline__ void cp_wait1() {
    asm volatile("cp.async.wait_group 1;" ::: "memory");
}
__device__ __forceinline__ void ldsm_x4(uint32_t addr, uint32_t* r) {
    asm volatile("ldmatrix.sync.aligned.m8n8.x4.shared.b16 {%0,%1,%2,%3}, [%4];"
        : "=r"(r[0]), "=r"(r[1]), "=r"(r[2]), "=r"(r[3]) : "r"(addr));
}
__device__ __forceinline__ void mma_bf16(float* d, const uint32_t* a, const uint32_t* b) {
    asm volatile(
        "mma.sync.aligned.m16n8k16.row.col.f32.bf16.bf16.f32 "
        "{%0,%1,%2,%3}, {%4,%5,%6,%7}, {%8,%9}, {%0,%1,%2,%3};"
        : "+f"(d[0]), "+f"(d[1]), "+f"(d[2]), "+f"(d[3])
        : "r"(a[0]), "r"(a[1]), "r"(a[2]), "r"(a[3]), "r"(b[0]), "r"(b[1]));
}
#define SWZ(o) ((o) ^ (((o) >> 3) & 0x70))

// ---------------- small kernels ------------------------------------------------
__global__ void init_kernel() {
    int i = blockIdx.x * blockDim.x + threadIdx.x;
    if (i < B_ * N_) { g_qn2[i] = 0.f; g_kn2[i] = 0.f; }
    if (i == 0) { g_sum = 0.0; g_cnt = 0ull; }
}

__global__ void mask_kernel(const float* __restrict__ cam) {
    int i = blockIdx.x * blockDim.x + threadIdx.x;
    if (i >= B_ * N_) return;
    int b = i / N_, p = i % N_;
    int oy = p / H_, ox = p % H_;
    const float step = 383.0f / 47.0f;
    float sy = (float)oy * step, sx = (float)ox * step;
    int y0 = min(max((int)floorf(sy), 0), CAM_ - 1);
    int x0 = min(max((int)floorf(sx), 0), CAM_ - 1);
    int y1 = min(y0 + 1, CAM_ - 1), x1 = min(x0 + 1, CAM_ - 1);
    float wy = sy - (float)y0, wx = sx - (float)x0;
    const float* cb = cam + (size_t)b * CAM_ * CAM_;
    float v00 = cb[y0 * CAM_ + x0]; v00 = (v00 == 255.0f) ? 0.f : v00;
    float v01 = cb[y0 * CAM_ + x1]; v01 = (v01 == 255.0f) ? 0.f : v01;
    float v10 = cb[y1 * CAM_ + x0]; v10 = (v10 == 255.0f) ? 0.f : v10;
    float v11 = cb[y1 * CAM_ + x1]; v11 = (v11 == 255.0f) ? 0.f : v11;
    float val = (1.f - wy) * ((1.f - wx) * v00 + wx * v01)
              + wy * ((1.f - wx) * v10 + wx * v11);
    g_mask[i] = (val > 0.f) ? 1.f : 0.f;
}

// x fp32 [C,N] -> g_xb bf16 [C,N] and g_xt bf16 [N,C]
__global__ void cvt_x_kernel(const float* __restrict__ x) {
    __shared__ float tile[32][33];
    int b = blockIdx.z;
    int n0 = blockIdx.x * 32, c0 = blockIdx.y * 32;
    int tx = threadIdx.x, ty = threadIdx.y;
    const float* xb = x + (size_t)b * C_ * N_;
    #pragma unroll
    for (int r = 0; r < 4; r++) {
        int c = c0 + ty + r * 8;
        float v = xb[(size_t)c * N_ + n0 + tx];
        tile[ty + r * 8][tx] = v;
        g_xb[(size_t)b * C_ * N_ + (size_t)c * N_ + n0 + tx] = __float2bfloat16(v);
    }
    __syncthreads();
    #pragma unroll
    for (int r = 0; r < 4; r++) {
        int n = n0 + ty + r * 8;
        g_xt[(size_t)b * N_ * C_ + (size_t)n * C_ + c0 + tx] =
            __float2bfloat16(tile[tx][ty + r * 8]);
    }
}

__global__ void cvt_w_kernel(const float* __restrict__ wq, const float* __restrict__ wk) {
    int i = blockIdx.x * 256 + threadIdx.x;
    if (i < C_ * C_) {
        g_wqb[i] = __float2bfloat16(wq[i]);
        g_wkb[i] = __float2bfloat16(wk[i]);
    }
}

// ---------------- HMMA GEMM: D[m,n] = sum_k A[m,k]*B[n,k] ---------------------
// A: [Mtot,K] bf16 K-major, B: [Ntot,K] bf16 K-major.
// EPI 0: v = acc + bias[col]; store bf16 Cb[row,col]; atomicAdd norm2[row] += v^2
// EPI 1: store fp32 Cf[row,col]
// EPI 2: loss: x = Xb[row,col] (bf16); r = (x - gamma*acc)^2 -> g_sum/g_cnt
template <int EPI>
__global__ void __launch_bounds__(256, 2)
mma_gemm(const __nv_bfloat16* __restrict__ Ag, const __nv_bfloat16* __restrict__ Bg,
         float* __restrict__ Cf, __nv_bfloat16* __restrict__ Cb,
         const float* __restrict__ bias, const __nv_bfloat16* __restrict__ Xb,
         float* __restrict__ norm2, const float* __restrict__ gptr,
         int K, int lda, int ldb, int ldc,
         long long sA, long long sB, long long sC, long long sX)
{
    extern __shared__ char dsm[];
    const uint32_t dbase = (smem_u32(dsm) + 1023u) & ~1023u;

    const int tid  = threadIdx.x;
    const int lane = tid & 31;
    const int wid  = tid >> 5;
    const int wm   = wid & 1;        // 2 warps along M (64 rows each)
    const int wn   = wid >> 1;       // 4 warps along N (32 cols each)
    const int bz = blockIdx.z;
    const int n0 = blockIdx.x * TN;
    const int m0 = blockIdx.y * TM;

    const __nv_bfloat16* Ab = Ag + (size_t)bz * sA + (size_t)m0 * lda;
    const __nv_bfloat16* Bp = Bg + (size_t)bz * sB + (size_t)n0 * ldb;

    // copy mapping: 4 rows per operand per thread, 16B each
    const int t_m = tid >> 3;        // 0..31
    const int t_k = tid & 7;         // 0..7 (16B slot)

    // ldmatrix address components
    uint32_t a_off[4], a_sw[4];
    #pragma unroll
    for (int mt = 0; mt < 4; mt++) {
        int r = wm * 64 + mt * 16 + (lane & 15);
        a_off[mt] = (uint32_t)r * 128u;
        a_sw[mt]  = (uint32_t)(r & 7) << 4;
    }
    const uint32_t a_hi = (uint32_t)(lane >> 4) << 4;     // k8 half -> +16B
    uint32_t b_off[2], b_sw[2];
    #pragma unroll
    for (int p = 0; p < 2; p++) {
        int r = wn * 32 + (2 * p + (lane >> 4)) * 8 + (lane & 7);
        b_off[p] = (uint32_t)r * 128u;
        b_sw[p]  = (uint32_t)(r & 7) << 4;
    }
    const uint32_t b_hi = (uint32_t)((lane >> 3) & 1) << 4;

    float acc[4][4][4] = {};

    const int KT = K / TK;

    // prologue: stage 0
    {
        uint32_t sb = dbase;
        #pragma unroll
        for (int i = 0; i < 4; i++) {
            int r = t_m + 32 * i;
            uint32_t so = SWZ((uint32_t)(r * 128 + t_k * 16));
            cp_async16(sb + so,          Ab + (size_t)r * lda + t_k * 8);
            cp_async16(sb + 16384 + so,  Bp + (size_t)r * ldb + t_k * 8);
        }
        cp_commit();
    }

    for (int t = 0; t < KT; t++) {
        const int s = t & 1;
        if (t + 1 < KT) {
            uint32_t sb = dbase + (uint32_t)((s ^ 1) * STAGE);
            const int kt = (t + 1) * TK;
            #pragma unroll
            for (int i = 0; i < 4; i++) {
                int r = t_m + 32 * i;
                uint32_t so = SWZ((uint32_t)(r * 128 + t_k * 16));
                cp_async16(sb + so,         Ab + (size_t)r * lda + kt + t_k * 8);
                cp_async16(sb + 16384 + so, Bp + (size_t)r * ldb + kt + t_k * 8);
            }
            cp_commit();
            cp_wait1();
        } else {
            cp_wait0();
        }
        __syncthreads();

        const uint32_t As = dbase + (uint32_t)(s * STAGE);
        const uint32_t Bs = As + 16384;
        #pragma unroll
        for (int ks = 0; ks < 4; ks++) {
            const uint32_t ko = (uint32_t)(ks * 32);      // 2 col16 slots * 16B
            uint32_t af[4][4], bf2[2][4];
            #pragma unroll
            for (int mt = 0; mt < 4; mt++)
                ldsm_x4(As + a_off[mt] + ((ko + a_hi) ^ a_sw[mt]), af[mt]);
            #pragma unroll
            for (int p = 0; p < 2; p++)
                ldsm_x4(Bs + b_off[p] + ((ko + b_hi) ^ b_sw[p]), bf2[p]);
            #pragma unroll
            for (int mt = 0; mt < 4; mt++)
                #pragma unroll
                for (int nt = 0; nt < 4; nt++)
                    mma_bf16(acc[mt][nt], af[mt], &bf2[nt >> 1][(nt & 1) * 2]);
        }
        __syncthreads();
    }

    // ---------------- epilogue ----------------
    const int g   = lane >> 2;
    const int tig = lane & 3;
    const int rbase = m0 + wm * 64 + g;
    const int cbase = n0 + wn * 32 + tig * 2;

    if (EPI == 0) {
        __nv_bfloat16* Cbb = Cb + (size_t)bz * sC;
        #pragma unroll
        for (int mt = 0; mt < 4; mt++) {
            int r0 = rbase + mt * 16, r1 = r0 + 8;
            float s0 = 0.f, s1 = 0.f;
            #pragma unroll
            for (int nt = 0; nt < 4; nt++) {
                int c = cbase + nt * 8;
                float b0 = __ldg(bias + c), b1 = __ldg(bias + c + 1);
                float v00 = acc[mt][nt][0] + b0, v01 = acc[mt][nt][1] + b1;
                float v10 = acc[mt][nt][2] + b0, v11 = acc[mt][nt][3] + b1;
                s0 += v00 * v00 + v01 * v01;
                s1 += v10 * v10 + v11 * v11;
                *(__nv_bfloat162*)(Cbb + (size_t)r0 * ldc + c) = __floats2bfloat162_rn(v00, v01);
                *(__nv_bfloat162*)(Cbb + (size_t)r1 * ldc + c) = __floats2bfloat162_rn(v10, v11);
            }
            s0 += __shfl_xor_sync(0xffffffffu, s0, 1);
            s0 += __shfl_xor_sync(0xffffffffu, s0, 2);
            s1 += __shfl_xor_sync(0xffffffffu, s1, 1);
            s1 += __shfl_xor_sync(0xffffffffu, s1, 2);
            if (tig == 0) {
                atomicAdd(&norm2[(size_t)bz * N_ + r0], s0);
                atomicAdd(&norm2[(size_t)bz * N_ + r1], s1);
            }
        }
    } else if (EPI == 1) {
        float* Cff = Cf + (size_t)bz * sC;
        #pragma unroll
        for (int mt = 0; mt < 4; mt++) {
            int r0 = rbase + mt * 16, r1 = r0 + 8;
            #pragma unroll
            for (int nt = 0; nt < 4; nt++) {
                int c = cbase + nt * 8;
                *(float2*)(Cff + (size_t)r0 * ldc + c) = make_float2(acc[mt][nt][0], acc[mt][nt][1]);
                *(float2*)(Cff + (size_t)r1 * ldc + c) = make_float2(acc[mt][nt][2], acc[mt][nt][3]);
            }
        }
    } else {
        const float gm = gptr[0];
        const __nv_bfloat16* Xp = Xb + (size_t)bz * sX;
        float lsum = 0.f;
        unsigned lcnt = 0;
        #pragma unroll
        for (int mt = 0; mt < 4; mt++) {
            int r0 = rbase + mt * 16, r1 = r0 + 8;
            #pragma unroll
            for (int nt = 0; nt < 4; nt++) {
                int c = cbase + nt * 8;
                __nv_bfloat162 x0 = *(const __nv_bfloat162*)(Xp + (size_t)r0 * ldc + c);
                __nv_bfloat162 x1 = *(const __nv_bfloat162*)(Xp + (size_t)r1 * ldc + c);
                float d0 = __bfloat162float(x0.x) - gm * acc[mt][nt][0];
                float d1 = __bfloat162float(x0.y) - gm * acc[mt][nt][1];
                float d2 = __bfloat162float(x1.x) - gm * acc[mt][nt][2];
                float d3 = __bfloat162float(x1.y) - gm * acc[mt][nt][3];
                float r00 = d0 * d0, r01 = d1 * d1, r10 = d2 * d2, r11 = d3 * d3;
                lsum += r00 + r01 + r10 + r11;
                lcnt += (r00 != 0.f) + (r01 != 0.f) + (r10 != 0.f) + (r11 != 0.f);
            }
        }
        #pragma unroll
        for (int o = 16; o > 0; o >>= 1) {
            lsum += __shfl_down_sync(0xffffffffu, lsum, o);
            lcnt += __shfl_down_sync(0xffffffffu, lcnt, o);
        }
        if (lane == 0) {
            atomicAdd(&g_sum, (double)lsum);
            atomicAdd(&g_cnt, (unsigned long long)lcnt);
        }
    }
}

// ---------------- softmax: fp32 energy -> bf16 attention ----------------------
__global__ void __launch_bounds__(256)
softmax_kernel()
{
    __shared__ float row[N_];
    __shared__ float red[256];
    const int n = blockIdx.x, b = blockIdx.y;
    const int tid = threadIdx.x;
    const float* Ar = g_att + ((size_t)b * N_ + n) * N_;
    __nv_bfloat16* Aw = g_attb + ((size_t)b * N_ + n) * N_;
    const float qs = g_qn2[b * N_ + n];

    float lmax = -INFINITY;
    for (int m = tid; m < N_; m += 256) {
        float v = Ar[m] * rsqrtf(qs * g_kn2[b * N_ + m]);
        row[m] = v;
        lmax = fmaxf(lmax, v);
    }
    red[tid] = lmax; __syncthreads();
    for (int s = 128; s > 0; s >>= 1) {
        if (tid < s) red[tid] = fmaxf(red[tid], red[tid + s]);
        __syncthreads();
    }
    float mx = red[0];
    __syncthreads();
    float lsum = 0.f;
    for (int m = tid; m < N_; m += 256) {
        float e = __expf(row[m] - mx);
        row[m] = e;
        lsum += e;
    }
    red[tid] = lsum; __syncthreads();
    for (int s = 128; s > 0; s >>= 1) {
        if (tid < s) red[tid] += red[tid + s];
        __syncthreads();
    }
    float scale = g_mask[b * N_ + n] / red[0];
    for (int m = tid; m < N_; m += 256)
        Aw[m] = __float2bfloat16(row[m] * scale);
}

__global__ void finalize_kernel(float* out) {
    out[0] = (float)(g_sum / (double)g_cnt);
}

// ---------------- launch --------------------------------------------------------
extern "C" void kernel_launch(void* const* d_in, const int* in_sizes, int n_in,
                              void* d_out, int out_size)
{
    const float* x     = (const float*)d_in[0];
    const float* cam   = (const float*)d_in[1];
    const float* Wq    = (const float*)d_in[2];
    const float* bq    = (const float*)d_in[3];
    const float* Wk    = (const float*)d_in[4];
    const float* bk    = (const float*)d_in[5];
    const float* gamma = (const float*)d_in[6];

    cudaFuncSetAttribute(mma_gemm<0>, cudaFuncAttributeMaxDynamicSharedMemorySize, SMEM_DYN);
    cudaFuncSetAttribute(mma_gemm<1>, cudaFuncAttributeMaxDynamicSharedMemorySize, SMEM_DYN);
    cudaFuncSetAttribute(mma_gemm<2>, cudaFuncAttributeMaxDynamicSharedMemorySize, SMEM_DYN);

    __nv_bfloat16 *pxt, *pxb, *pwq, *pwk, *pqr, *pkr, *pattb;
    float *patt, *pqn2, *pkn2;
    cudaGetSymbolAddress((void**)&pxt,   g_xt);
    cudaGetSymbolAddress((void**)&pxb,   g_xb);
    cudaGetSymbolAddress((void**)&pwq,   g_wqb);
    cudaGetSymbolAddress((void**)&pwk,   g_wkb);
    cudaGetSymbolAddress((void**)&pqr,   g_qr);
    cudaGetSymbolAddress((void**)&pkr,   g_kr);
    cudaGetSymbolAddress((void**)&pattb, g_attb);
    cudaGetSymbolAddress((void**)&patt,  g_att);
    cudaGetSymbolAddress((void**)&pqn2,  g_qn2);
    cudaGetSymbolAddress((void**)&pkn2,  g_kn2);

    const long long sNC = (long long)N_ * C_;
    const long long sCN = (long long)C_ * N_;
    const long long sNN = (long long)N_ * N_;

    init_kernel<<<(B_ * N_ + 255) / 256, 256>>>();
    mask_kernel<<<(B_ * N_ + 255) / 256, 256>>>(cam);
    cvt_w_kernel<<<(C_ * C_ + 255) / 256, 256>>>(Wq, Wk);
    cvt_x_kernel<<<dim3(N_ / 32, C_ / 32, B_), dim3(32, 8)>>>(x);

    // q[n,oc] = sum_c xt[n,c]*Wq[oc,c] + bq[oc]; rownorm2 -> qn2; bf16 out
    mma_gemm<0><<<dim3(C_ / TN, N_ / TM, B_), 256, SMEM_DYN>>>(
        pxt, pwq, nullptr, pqr, bq, nullptr, pqn2, nullptr,
        C_, C_, C_, C_, sNC, 0LL, sNC, 0LL);
    mma_gemm<0><<<dim3(C_ / TN, N_ / TM, B_), 256, SMEM_DYN>>>(
        pxt, pwk, nullptr, pkr, bk, nullptr, pkn2, nullptr,
        C_, C_, C_, C_, sNC, 0LL, sNC, 0LL);
    // energy[n,m] = sum_c q[n,c]*k[m,c]; fp32 out
    mma_gemm<1><<<dim3(N_ / TN, N_ / TM, B_), 256, SMEM_DYN>>>(
        pqr, pkr, patt, nullptr, nullptr, nullptr, nullptr, nullptr,
        C_, C_, C_, N_, sNC, sNC, sNN, 0LL);
    // softmax + mask -> bf16 attention
    softmax_kernel<<<dim3(N_, B_), 256>>>();
    // loss: D[n,c] = sum_m att[n,m]*xb[c,m]; X read = xt[n,c]
    mma_gemm<2><<<dim3(C_ / TN, N_ / TM, B_), 256, SMEM_DYN>>>(
        pattb, pxb, nullptr, nullptr, nullptr, pxt, nullptr, gamma,
        N_, N_, N_, C_, sNN, sCN, 0LL, sNC);

    finalize_kernel<<<1, 1>>>((float*)d_out);
}